// round 7
// baseline (speedup 1.0000x reference)
#include <cuda_runtime.h>

// Problem shape (fixed by the dataset)
#define BB 256
#define SS 2048
#define HH 128
#define NB 2
#define NTHREADS 512
#define DT 0.1f
#define PAD 36           // floats per 32-float chunk (16B pad kills bank conflicts)
#define HPAD (4 * PAD)   // 144 floats per padded state vector

typedef unsigned long long ull;

// Packed fp32x2 FMA (Blackwell): two fp32 MACs per instruction.
__device__ __forceinline__ ull ffma2(ull a, ull b, ull c) {
    ull d;
    asm("fma.rn.f32x2 %0, %1, %2, %3;" : "=l"(d) : "l"(a), "l"(b), "l"(c));
    return d;
}
__device__ __forceinline__ float fold2(ull a) {
    float lo, hi;
    asm("mov.b64 {%0, %1}, %2;" : "=f"(lo), "=f"(hi) : "l"(a));
    return lo + hi;
}
__device__ __forceinline__ float tanha(float x) {
    float t; asm("tanh.approx.f32 %0, %1;" : "=f"(t) : "f"(x)); return t;
}
__device__ __forceinline__ float shx(float v, int m) {
    return __shfl_xor_sync(0xffffffffu, v, m);
}

// Phase-A matvec pass over one batch's h chunk (16 floats at v):
// 2 row-slots x 2 matrices -> 4 folded partials.
__device__ __forceinline__ void mvA(const ulonglong2 (&wk)[2][4],
                                    const ulonglong2 (&ws)[2][4],
                                    const float* v, float (&fk)[2], float (&fs)[2]) {
    const ulonglong2* pv = reinterpret_cast<const ulonglong2*>(v);
    const ulonglong2 v0 = pv[0], v1 = pv[1], v2 = pv[2], v3 = pv[3];
#pragma unroll
    for (int j = 0; j < 2; j++) {
        ull a = ffma2(wk[j][0].x, v0.x, 0ULL);
        a = ffma2(wk[j][0].y, v0.y, a);
        a = ffma2(wk[j][1].x, v1.x, a);
        a = ffma2(wk[j][1].y, v1.y, a);
        a = ffma2(wk[j][2].x, v2.x, a);
        a = ffma2(wk[j][2].y, v2.y, a);
        a = ffma2(wk[j][3].x, v3.x, a);
        a = ffma2(wk[j][3].y, v3.y, a);
        fk[j] = fold2(a);
        ull b = ffma2(ws[j][0].x, v0.x, 0ULL);
        b = ffma2(ws[j][0].y, v0.y, b);
        b = ffma2(ws[j][1].x, v1.x, b);
        b = ffma2(ws[j][1].y, v1.y, b);
        b = ffma2(ws[j][2].x, v2.x, b);
        b = ffma2(ws[j][2].y, v2.y, b);
        b = ffma2(ws[j][3].x, v3.x, b);
        b = ffma2(ws[j][3].y, v3.y, b);
        fs[j] = fold2(b);
    }
}
// Phase-B matvec pass (W_rec only): 2 row-slots -> 2 folded partials.
__device__ __forceinline__ void mvB(const ulonglong2 (&wr)[2][4],
                                    const float* v, float (&fr)[2]) {
    const ulonglong2* pv = reinterpret_cast<const ulonglong2*>(v);
    const ulonglong2 v0 = pv[0], v1 = pv[1], v2 = pv[2], v3 = pv[3];
#pragma unroll
    for (int j = 0; j < 2; j++) {
        ull a = ffma2(wr[j][0].x, v0.x, 0ULL);
        a = ffma2(wr[j][0].y, v0.y, a);
        a = ffma2(wr[j][1].x, v1.x, a);
        a = ffma2(wr[j][1].y, v1.y, a);
        a = ffma2(wr[j][2].x, v2.x, a);
        a = ffma2(wr[j][2].y, v2.y, a);
        a = ffma2(wr[j][3].x, v3.x, a);
        a = ffma2(wr[j][3].y, v3.y, a);
        fr[j] = fold2(a);
    }
}
// Phase-A reduce-scatter: 8 partials -> this lane's (row, matrix, batch) dot.
__device__ __forceinline__ float redA(const float (&fkf)[2], const float (&fsf)[2],
                                      const float (&fks)[2], const float (&fss)[2]) {
    float Kf = fkf[0] + shx(fkf[1], 4);   // xor4: row scatter (slot-permuted)
    float Sf = fsf[0] + shx(fsf[1], 4);
    float Ks = fks[0] + shx(fks[1], 4);
    float Ss = fss[0] + shx(fss[1], 4);
    Kf += shx(Sf, 2);                     // xor2: matrix scatter (pair-swapped)
    Ks += shx(Ss, 2);
    return Kf + shx(Ks, 1);               // xor1: batch scatter (order-swapped)
}
// Phase-B reduce: row scatter, matrix-level allreduce, batch scatter.
__device__ __forceinline__ float redB(const float (&frf)[2], const float (&frs)[2]) {
    float Rf = frf[0] + shx(frf[1], 4);
    float Rs = frs[0] + shx(frs[1], 4);
    Rf += shx(Rf, 2);
    Rs += shx(Rs, 2);
    return Rf + shx(Rs, 1);
}

__global__ void __launch_bounds__(NTHREADS, 1)
liquid_scan_kernel(const float* __restrict__ x,
                   const float* __restrict__ W_in, const float* __restrict__ b_in,
                   const float* __restrict__ W_rec, const float* __restrict__ b_rec,
                   const float* __restrict__ tau,
                   const float* __restrict__ W_att, const float* __restrict__ b_att,
                   const float* __restrict__ W_ev, const float* __restrict__ b_ev,
                   const float* __restrict__ W_acc, const float* __restrict__ b_acc,
                   const float* __restrict__ W_out, const float* __restrict__ b_out,
                   float* __restrict__ out) {
    __shared__ __align__(16) float2 xe[NB][SS];      // (x, ew) pairs (32 KB)
    __shared__ __align__(16) float hs[NB][HPAD];     // hidden state (padded chunks)
    __shared__ __align__(16) float hatts[NB][HPAD];  // h * att (padded chunks)

    const int tid = threadIdx.x;
    const int g  = tid >> 3;         // row-pair group: rows 2g, 2g+1
    const int L  = tid & 7;          // lane within 8-lane reduce group
    const int b2 = (L >> 2) & 1;     // row bit (scattered at xor4)
    const int b1 = (L >> 1) & 1;     // matrix bit (scattered at xor2)
    const int b0 = L & 1;            // batch bit (scattered at xor1)
    const int q  = tid & 3;          // lane role (= b1,b0)
    const int p  = b0;               // this lane's batch
    const int h  = tid >> 2;         // owned row (= 2g + b2)
    const int bb = blockIdx.x * NB;
    const int vb = (L >> 1) * PAD + (L & 1) * 16;   // padded float offset of 16-col chunk
    const int hoff = (h >> 5) * PAD + (h & 31);     // padded scalar index for row h

    // ---- stage x into xe[.].x
    {
        const float* xg0 = x + (size_t)bb * SS;
        const float* xg1 = xg0 + SS;
#pragma unroll
        for (int k = 0; k < SS / NTHREADS; k++) {
            const int s = tid + k * NTHREADS;
            xe[0][s].x = xg0[s];
            xe[1][s].x = xg1[s];
        }
    }
    if (tid < HPAD) { hs[0][tid] = 0.0f; hs[1][tid] = 0.0f; }
    __syncthreads();

    // ---- event weights into xe[.].y AND the event_weights output
    {
        const float wev0 = W_ev[0], wev1 = W_ev[1], bev = b_ev[0];
        float* out_ew = out + BB;
#pragma unroll
        for (int k = 0; k < SS / NTHREADS; k++) {
            const int s = tid + k * NTHREADS;
#pragma unroll
            for (int b = 0; b < NB; b++) {
                float e = 0.0f;
                if (s > 0) {
                    float t = tanha(0.5f * (wev0 * xe[b][s].x + wev1 * xe[b][s - 1].x + bev));
                    e = fmaf(0.5f, t, 0.5f);
                }
                xe[b][s].y = e;
                out_ew[(size_t)(bb + b) * SS + s] = e;
            }
        }
    }

    // ---- weights into registers, butterfly-permuted (96 regs):
    // slot j holds row 2g + (b2 ^ j); kept/sent matrices per b1.
    const float* WmK = b1 ? W_acc : W_att;
    const float* WmS = b1 ? W_att : W_acc;
    ulonglong2 wk[2][4], wsn[2][4], wrr[2][4];
#pragma unroll
    for (int j = 0; j < 2; j++) {
        const int row = 2 * g + (b2 ^ j);
        const ulonglong2* pk = reinterpret_cast<const ulonglong2*>(WmK + row * HH + 16 * L);
        const ulonglong2* ps = reinterpret_cast<const ulonglong2*>(WmS + row * HH + 16 * L);
        const ulonglong2* pr = reinterpret_cast<const ulonglong2*>(W_rec + row * HH + 16 * L);
#pragma unroll
        for (int k = 0; k < 4; k++) { wk[j][k] = pk[k]; wsn[j][k] = ps[k]; wrr[j][k] = pr[k]; }
    }

    const float pA_bias = (q < 2) ? b_att[h] : b_acc[h];
    const float brec = b_rec[h];
    const float win  = W_in[h];
    const float bin  = b_in[h];
    const float itau = 1.0f / fminf(fmaxf(tau[h], 0.1f), 10.0f);

    // Batch-order pointers (first = lane's own batch, scattered at xor1).
    const float* hAf = &hs[b0][vb];
    const float* hAs = &hs[b0 ^ 1][vb];
    const float* hBf = &hatts[b0][vb];
    const float* hBs = &hatts[b0 ^ 1][vb];
    const float2* xep = &xe[p][0];

    float hprev = 0.0f;  // own-batch hidden value for row h (register-carried)
    float accq = 0.0f;   // acc state: q2 = acc[b0], q3 = acc[b1]
    float ewpq = 0.0f;   // previous step's event weight (pipelined acc)

    __syncthreads();

#pragma unroll 1
    for (int s = 0; s < SS; s++) {
        const float2 xev = xep[s];   // (x_t, ew_t) for this lane's batch

        // ---- phase A: att + acc matvecs on h_s
        float fkf[2], fsf[2], fks[2], fss[2];
        mvA(wk, wsn, hAf, fkf, fsf);
        mvA(wk, wsn, hAs, fks, fss);
        const float F = redA(fkf, fsf, fks, fss);
        // lane role: q0->att(b0), q1->att(b1), q2->acc-tanh(b0), q3->acc-tanh(b1)
        const float inA = F + pA_bias;
        const float tA = tanha((q < 2) ? 0.5f * inA : inA);
        const float vA = (q < 2) ? fmaf(0.5f, tA, 0.5f) : tA;
        if (q < 2) hatts[p][hoff] = hprev * vA;    // q0 -> b0, q1 -> b1
        accq = 0.9f * accq + 0.1f * vA * ewpq;     // meaningful on q2/q3
        __syncthreads();

        // ---- phase B: recurrence matvec on h*att, state update
        float frf[2], frs[2];
        mvB(wrr, hBf, frf);
        mvB(wrr, hBs, frs);
        const float R = redB(frf, frs);
        // roles: q0->rec(b0), q1->rec(b1), q2->ic(b0), q3->ic(b1)
        const float inB = (q & 2) ? fmaf(win, xev.x, bin) : (R + brec);
        const float tB = tanha(inB);
        const float icx = shx(tB, 2);
        const float hn = hprev + DT * ((icx + tB - hprev) * itau) * (1.0f + xev.y);
        if (q < 2) hs[p][hoff] = hn;
        hprev = hn;
        ewpq = xev.y;
        __syncthreads();
    }

    // ---- trailing acc update: tanh(W_acc @ h_S) with ew_{S-1}
    {
        float fkf[2], fsf[2], fks[2], fss[2];
        mvA(wk, wsn, hAf, fkf, fsf);
        mvA(wk, wsn, hAs, fks, fss);
        const float F = redA(fkf, fsf, fks, fss);
        const float t = tanha(F + pA_bias);        // valid on q2/q3 (bias = bacc)
        accq = 0.9f * accq + 0.1f * t * ewpq;
    }

    // ---- epilogue: out[b] = (h_f + acc_f) . W_out + b_out
    if (q & 2) hatts[p][hoff] = accq;   // q2 -> acc[b0], q3 -> acc[b1]
    __syncthreads();
    const int w = tid >> 5, l = tid & 31;
    if (w < NB) {
        float pacc = 0.0f;
#pragma unroll
        for (int i = 0; i < HH / 32; i++) {
            const int jo = i * PAD + l;
            pacc += (hs[w][jo] + hatts[w][jo]) * W_out[l + 32 * i];
        }
#pragma unroll
        for (int o = 16; o; o >>= 1) pacc += shx(pacc, o);
        if (l == 0) out[bb + w] = pacc + b_out[0];
    }
}

extern "C" void kernel_launch(void* const* d_in, const int* in_sizes, int n_in,
                              void* d_out, int out_size) {
    const float* x     = (const float*)d_in[0];
    const float* W_in  = (const float*)d_in[1];
    const float* b_in  = (const float*)d_in[2];
    const float* W_rec = (const float*)d_in[3];
    const float* b_rec = (const float*)d_in[4];
    const float* tau   = (const float*)d_in[5];
    const float* W_att = (const float*)d_in[6];
    const float* b_att = (const float*)d_in[7];
    const float* W_ev  = (const float*)d_in[8];
    const float* b_ev  = (const float*)d_in[9];
    const float* W_acc = (const float*)d_in[10];
    const float* b_acc = (const float*)d_in[11];
    const float* W_out = (const float*)d_in[12];
    const float* b_out = (const float*)d_in[13];
    float* out = (float*)d_out;

    liquid_scan_kernel<<<BB / NB, NTHREADS>>>(x, W_in, b_in, W_rec, b_rec, tau,
                                              W_att, b_att, W_ev, b_ev,
                                              W_acc, b_acc, W_out, b_out, out);
}

// round 9
// speedup vs baseline: 1.5599x; 1.5599x over previous
#include <cuda_runtime.h>

// Problem shape (fixed by the dataset)
#define BB 256
#define SS 2048
#define HH 128
#define NB 2
#define NTHREADS 512
#define DT 0.1f
#define PAD 36           // floats per 32-float chunk (16B pad kills bank conflicts)
#define HPAD (4 * PAD)   // 144 floats per padded state vector

typedef unsigned long long ull;

// Packed fp32x2 FMA (Blackwell): two fp32 MACs per instruction.
__device__ __forceinline__ ull ffma2(ull a, ull b, ull c) {
    ull d;
    asm("fma.rn.f32x2 %0, %1, %2, %3;" : "=l"(d) : "l"(a), "l"(b), "l"(c));
    return d;
}
__device__ __forceinline__ float tanha(float x) {
    float t; asm("tanh.approx.f32 %0, %1;" : "=f"(t) : "f"(x)); return t;
}

// Reduce two packed row-partials (rows r0, r1 of this thread's group) across
// the 8-lane column group. Returns the full dot for THIS lane's row
// (row = 2g + bit2), replicated over the 4 q-lanes.
__device__ __forceinline__ float redq2(ull a0, ull a1, bool hiRow) {
    float l0, h0, l1, h1;
    asm("mov.b64 {%0, %1}, %2;" : "=f"(l0), "=f"(h0) : "l"(a0));
    asm("mov.b64 {%0, %1}, %2;" : "=f"(l1), "=f"(h1) : "l"(a1));
    const float s0 = l0 + h0;
    const float s1 = l1 + h1;
    // xor-4 exchange: low lanes keep row0 (send row1 partial), high lanes keep row1.
    const float x = hiRow ? s0 : s1;
    const float r = __shfl_xor_sync(0xffffffffu, x, 4);
    float s = (hiRow ? s1 : s0) + r;
    s += __shfl_xor_sync(0xffffffffu, s, 2);
    s += __shfl_xor_sync(0xffffffffu, s, 1);
    return s;
}

__global__ void __launch_bounds__(NTHREADS, 1)
liquid_scan_kernel(const float* __restrict__ x,
                   const float* __restrict__ W_in, const float* __restrict__ b_in,
                   const float* __restrict__ W_rec, const float* __restrict__ b_rec,
                   const float* __restrict__ tau,
                   const float* __restrict__ W_att, const float* __restrict__ b_att,
                   const float* __restrict__ W_ev, const float* __restrict__ b_ev,
                   const float* __restrict__ W_acc, const float* __restrict__ b_acc,
                   const float* __restrict__ W_out, const float* __restrict__ b_out,
                   float* __restrict__ out) {
    __shared__ __align__(16) float2 xe[NB][SS];      // fused (x, ew) pairs
    __shared__ __align__(16) float hs[NB][HPAD];     // hidden state (padded chunks)
    __shared__ __align__(16) float hatts[NB][HPAD];  // h * att (padded chunks)

    const int tid = threadIdx.x;
    const int g  = tid >> 3;      // row-pair group: rows 2g, 2g+1
    const int c  = tid & 7;       // 16-col block index within the row group
    const int h  = tid >> 2;      // row this lane owns after reduction (= 2g + bit2)
    const int q  = tid & 3;       // lane role
    const int p  = q & 1;         // batch parity for this lane's role
    const bool hiRow = (tid >> 2) & 1;
    const int b0 = blockIdx.x * NB;
    const int vbase = 16 * c + 4 * (c >> 1);          // padded float offset of col block
    const int hoff = (h >> 5) * PAD + (h & 31);       // padded scalar index for row h

    // ---- stage x rows into smem (.x components)
    {
        const float* xg0 = x + (size_t)b0 * SS;
        const float* xg1 = xg0 + SS;
#pragma unroll
        for (int k = 0; k < SS / NTHREADS; k++) {
            const int s = tid + k * NTHREADS;
            xe[0][s].x = xg0[s];
            xe[1][s].x = xg1[s];
        }
    }
    if (tid < HPAD) { hs[0][tid] = 0.0f; hs[1][tid] = 0.0f; }
    __syncthreads();

    // ---- precompute event weights into xe[.].y AND the event_weights output
    {
        const float wev0 = W_ev[0], wev1 = W_ev[1], bev = b_ev[0];
        float* out_ew = out + BB;
#pragma unroll
        for (int k = 0; k < SS / NTHREADS; k++) {
            const int s = tid + k * NTHREADS;
#pragma unroll
            for (int b = 0; b < NB; b++) {
                float e = 0.0f;
                if (s > 0) {
                    float t = tanha(0.5f * (wev0 * xe[b][s].x + wev1 * xe[b][s - 1].x + bev));
                    e = fmaf(0.5f, t, 0.5f);
                }
                xe[b][s].y = e;
                out_ew[(size_t)(b0 + b) * SS + s] = e;
            }
        }
    }

    // ---- weights into registers: 3 mats x 2 rows x 16 cols = 96 fp32
    ulonglong2 wa[2][4], wr[2][4], wc[2][4];
#pragma unroll
    for (int r = 0; r < 2; r++) {
        const int row = 2 * g + r;
        const ulonglong2* Wa = reinterpret_cast<const ulonglong2*>(W_att + row * HH + 16 * c);
        const ulonglong2* Wr = reinterpret_cast<const ulonglong2*>(W_rec + row * HH + 16 * c);
        const ulonglong2* Wc = reinterpret_cast<const ulonglong2*>(W_acc + row * HH + 16 * c);
#pragma unroll
        for (int k = 0; k < 4; k++) { wa[r][k] = Wa[k]; wr[r][k] = Wr[k]; wc[r][k] = Wc[k]; }
    }
    // Lane-role-folded scalars.
    const float pA_bias = (q < 2) ? b_att[h] : b_acc[h];   // phase A bias
    const float brec = b_rec[h];
    const float win  = W_in[h];
    const float bin  = b_in[h];
    const float itau = 1.0f / fminf(fmaxf(tau[h], 0.1f), 10.0f);

    float hprev = 0.0f;  // h[p][h] carried in a register (was an LDS every step)
    float accq = 0.0f;   // acc state: q2 holds acc[batch0], q3 holds acc[batch1]
    float ewpq = 0.0f;   // previous step's event weight for this lane's batch

    __syncthreads();

#pragma unroll 1
    for (int s = 0; s < SS; s++) {
        const float2 xev = xe[p][s];   // (x_t, ew_t) for this lane's batch

        // ---- phase A: att + acc matvecs on h_s, batch-sequential
        float A0, C0, A1, C1;
        {
            ull aa0 = 0, aa1 = 0, ac0 = 0, ac1 = 0;
#pragma unroll
            for (int k = 0; k < 4; k++) {
                const ulonglong2 hv = *reinterpret_cast<const ulonglong2*>(&hs[0][vbase + 4 * k]);
                aa0 = ffma2(wa[0][k].x, hv.x, aa0); aa0 = ffma2(wa[0][k].y, hv.y, aa0);
                aa1 = ffma2(wa[1][k].x, hv.x, aa1); aa1 = ffma2(wa[1][k].y, hv.y, aa1);
                ac0 = ffma2(wc[0][k].x, hv.x, ac0); ac0 = ffma2(wc[0][k].y, hv.y, ac0);
                ac1 = ffma2(wc[1][k].x, hv.x, ac1); ac1 = ffma2(wc[1][k].y, hv.y, ac1);
            }
            A0 = redq2(aa0, aa1, hiRow);
            C0 = redq2(ac0, ac1, hiRow);
        }
        {
            ull aa0 = 0, aa1 = 0, ac0 = 0, ac1 = 0;
#pragma unroll
            for (int k = 0; k < 4; k++) {
                const ulonglong2 hv = *reinterpret_cast<const ulonglong2*>(&hs[1][vbase + 4 * k]);
                aa0 = ffma2(wa[0][k].x, hv.x, aa0); aa0 = ffma2(wa[0][k].y, hv.y, aa0);
                aa1 = ffma2(wa[1][k].x, hv.x, aa1); aa1 = ffma2(wa[1][k].y, hv.y, aa1);
                ac0 = ffma2(wc[0][k].x, hv.x, ac0); ac0 = ffma2(wc[0][k].y, hv.y, ac0);
                ac1 = ffma2(wc[1][k].x, hv.x, ac1); ac1 = ffma2(wc[1][k].y, hv.y, ac1);
            }
            A1 = redq2(aa0, aa1, hiRow);
            C1 = redq2(ac0, ac1, hiRow);
        }

        // lane roles: q0->att(b0), q1->att(b1), q2->acc-tanh(b0), q3->acc-tanh(b1)
        const float inA = ((q & 2) ? (p ? C1 : C0) : (p ? A1 : A0)) + pA_bias;
        const float tA = tanha((q < 2) ? 0.5f * inA : inA);
        const float vA = (q < 2) ? fmaf(0.5f, tA, 0.5f) : tA;

        if (q < 2) hatts[p][hoff] = hprev * vA;  // q0 writes b0, q1 writes b1
        accq = 0.9f * accq + 0.1f * vA * ewpq;   // meaningful on q2/q3 only
        __syncthreads();

        // ---- phase B: recurrence matvec on h*att, state update
        float R0, R1;
        {
            ull ar0 = 0, ar1 = 0;
#pragma unroll
            for (int k = 0; k < 4; k++) {
                const ulonglong2 hv = *reinterpret_cast<const ulonglong2*>(&hatts[0][vbase + 4 * k]);
                ar0 = ffma2(wr[0][k].x, hv.x, ar0); ar0 = ffma2(wr[0][k].y, hv.y, ar0);
                ar1 = ffma2(wr[1][k].x, hv.x, ar1); ar1 = ffma2(wr[1][k].y, hv.y, ar1);
            }
            R0 = redq2(ar0, ar1, hiRow);
        }
        {
            ull ar0 = 0, ar1 = 0;
#pragma unroll
            for (int k = 0; k < 4; k++) {
                const ulonglong2 hv = *reinterpret_cast<const ulonglong2*>(&hatts[1][vbase + 4 * k]);
                ar0 = ffma2(wr[0][k].x, hv.x, ar0); ar0 = ffma2(wr[0][k].y, hv.y, ar0);
                ar1 = ffma2(wr[1][k].x, hv.x, ar1); ar1 = ffma2(wr[1][k].y, hv.y, ar1);
            }
            R1 = redq2(ar0, ar1, hiRow);
        }

        // lane roles: q0->rec(b0), q1->rec(b1), q2->ic(b0), q3->ic(b1)
        const float inB = (q & 2) ? fmaf(win, xev.x, bin) : ((p ? R1 : R0) + brec);
        const float tB = tanha(inB);
        const float icx = __shfl_xor_sync(0xffffffffu, tB, 2);  // q0<-ic0, q1<-ic1
        const float hn = hprev + DT * ((icx + tB - hprev) * itau) * (1.0f + xev.y);
        if (q < 2) hs[p][hoff] = hn;             // q0 writes b0, q1 writes b1
        hprev = hn;
        ewpq = xev.y;
        __syncthreads();
    }

    // ---- trailing acc update: tanh(W_acc @ h_S) with ew_{S-1}
    {
        ull c00 = 0, c01 = 0, c10 = 0, c11 = 0;
#pragma unroll
        for (int k = 0; k < 4; k++) {
            const ulonglong2 h0 = *reinterpret_cast<const ulonglong2*>(&hs[0][vbase + 4 * k]);
            const ulonglong2 h1 = *reinterpret_cast<const ulonglong2*>(&hs[1][vbase + 4 * k]);
            c00 = ffma2(wc[0][k].x, h0.x, c00); c00 = ffma2(wc[0][k].y, h0.y, c00);
            c01 = ffma2(wc[1][k].x, h0.x, c01); c01 = ffma2(wc[1][k].y, h0.y, c01);
            c10 = ffma2(wc[0][k].x, h1.x, c10); c10 = ffma2(wc[0][k].y, h1.y, c10);
            c11 = ffma2(wc[1][k].x, h1.x, c11); c11 = ffma2(wc[1][k].y, h1.y, c11);
        }
        const float C0 = redq2(c00, c01, hiRow);
        const float C1 = redq2(c10, c11, hiRow);
        const float t = tanha((p ? C1 : C0) + pA_bias);  // valid on q2/q3 (bias=bacc)
        accq = 0.9f * accq + 0.1f * t * ewpq;
    }

    // ---- epilogue: out[b] = (h_f + acc_f) . W_out + b_out
    if (q & 2) hatts[p][hoff] = accq;   // q2 -> acc[b0], q3 -> acc[b1]
    __syncthreads();
    const int w = tid >> 5, l = tid & 31;
    if (w < NB) {
        float pacc = 0.0f;
#pragma unroll
        for (int i = 0; i < HH / 32; i++) {
            const int jo = i * PAD + l;
            pacc += (hs[w][jo] + hatts[w][jo]) * W_out[l + 32 * i];
        }
#pragma unroll
        for (int o = 16; o; o >>= 1) pacc += __shfl_xor_sync(0xffffffffu, pacc, o);
        if (l == 0) out[b0 + w] = pacc + b_out[0];
    }
}

extern "C" void kernel_launch(void* const* d_in, const int* in_sizes, int n_in,
                              void* d_out, int out_size) {
    const float* x     = (const float*)d_in[0];
    const float* W_in  = (const float*)d_in[1];
    const float* b_in  = (const float*)d_in[2];
    const float* W_rec = (const float*)d_in[3];
    const float* b_rec = (const float*)d_in[4];
    const float* tau   = (const float*)d_in[5];
    const float* W_att = (const float*)d_in[6];
    const float* b_att = (const float*)d_in[7];
    const float* W_ev  = (const float*)d_in[8];
    const float* b_ev  = (const float*)d_in[9];
    const float* W_acc = (const float*)d_in[10];
    const float* b_acc = (const float*)d_in[11];
    const float* W_out = (const float*)d_in[12];
    const float* b_out = (const float*)d_in[13];
    float* out = (float*)d_out;

    liquid_scan_kernel<<<BB / NB, NTHREADS>>>(x, W_in, b_in, W_rec, b_rec, tau,
                                              W_att, b_att, W_ev, b_ev,
                                              W_acc, b_acc, W_out, b_out, out);
}

// round 11
// speedup vs baseline: 1.5612x; 1.0008x over previous
#include <cuda_runtime.h>

// Problem shape (fixed by the dataset)
#define BB 256
#define SS 2048
#define HH 128
#define NB 2
#define NTHREADS 512
#define DT 0.1f
#define PAD 36            // floats per 32-float chunk (16B pad kills bank conflicts)
#define HPAD 160          // padded state row: 4*36 + 16 tail pad (160 % 32 == 0)
#define XSS (SS + 4)      // padded xe row (8-bank shift between batches)

typedef unsigned long long ull;

// Packed fp32x2 FMA (Blackwell): two fp32 MACs per instruction.
__device__ __forceinline__ ull ffma2(ull a, ull b, ull c) {
    ull d;
    asm("fma.rn.f32x2 %0, %1, %2, %3;" : "=l"(d) : "l"(a), "l"(b), "l"(c));
    return d;
}
__device__ __forceinline__ float fold2(ull a) {
    float lo, hi;
    asm("mov.b64 {%0, %1}, %2;" : "=f"(lo), "=f"(hi) : "l"(a));
    return lo + hi;
}
__device__ __forceinline__ float tanha(float x) {
    float t; asm("tanh.approx.f32 %0, %1;" : "=f"(t) : "f"(x)); return t;
}
__device__ __forceinline__ float shx(float v, int m) {
    return __shfl_xor_sync(0xffffffffu, v, m);
}

// Partial reduce: slot-permuted xor4 (row exchange, no selects) + xor2.
// Result: this lane's row, summed over the 4 col-blocks with blockbit0 == p.
__device__ __forceinline__ float redp(ull a0, ull a1) {
    float s = fold2(a0) + shx(fold2(a1), 4);
    s += shx(s, 2);
    return s;
}

// Phase-A pass over one batch's h chunk: att + acc partials (2 row slots each).
__device__ __forceinline__ void passA(const ulonglong2 (&wa)[2][4],
                                      const ulonglong2 (&wc)[2][4],
                                      const float* v, float& PA, float& PC) {
    ull aa0 = 0, aa1 = 0, ac0 = 0, ac1 = 0;
#pragma unroll
    for (int k = 0; k < 4; k++) {
        const ulonglong2 hv = *reinterpret_cast<const ulonglong2*>(v + 4 * k);
        aa0 = ffma2(wa[0][k].x, hv.x, aa0); aa0 = ffma2(wa[0][k].y, hv.y, aa0);
        aa1 = ffma2(wa[1][k].x, hv.x, aa1); aa1 = ffma2(wa[1][k].y, hv.y, aa1);
        ac0 = ffma2(wc[0][k].x, hv.x, ac0); ac0 = ffma2(wc[0][k].y, hv.y, ac0);
        ac1 = ffma2(wc[1][k].x, hv.x, ac1); ac1 = ffma2(wc[1][k].y, hv.y, ac1);
    }
    PA = redp(aa0, aa1);
    PC = redp(ac0, ac1);
}
// Phase-B pass (W_rec only).
__device__ __forceinline__ float passB(const ulonglong2 (&wr)[2][4], const float* v) {
    ull ar0 = 0, ar1 = 0;
#pragma unroll
    for (int k = 0; k < 4; k++) {
        const ulonglong2 hv = *reinterpret_cast<const ulonglong2*>(v + 4 * k);
        ar0 = ffma2(wr[0][k].x, hv.x, ar0); ar0 = ffma2(wr[0][k].y, hv.y, ar0);
        ar1 = ffma2(wr[1][k].x, hv.x, ar1); ar1 = ffma2(wr[1][k].y, hv.y, ar1);
    }
    return redp(ar0, ar1);
}

__global__ void __launch_bounds__(NTHREADS, 1)
liquid_scan_kernel(const float* __restrict__ x,
                   const float* __restrict__ W_in, const float* __restrict__ b_in,
                   const float* __restrict__ W_rec, const float* __restrict__ b_rec,
                   const float* __restrict__ tau,
                   const float* __restrict__ W_att, const float* __restrict__ b_att,
                   const float* __restrict__ W_ev, const float* __restrict__ b_ev,
                   const float* __restrict__ W_acc, const float* __restrict__ b_acc,
                   const float* __restrict__ W_out, const float* __restrict__ b_out,
                   float* __restrict__ out) {
    __shared__ __align__(16) float2 xe[NB][XSS];     // fused (x, ew), padded rows
    __shared__ __align__(16) float hs[NB][HPAD];     // hidden state (padded)
    __shared__ __align__(16) float hatts[NB][HPAD];  // h * att (padded)

    const int tid = threadIdx.x;
    const int g  = tid >> 3;      // row-pair group: rows 2g, 2g+1
    const int c  = tid & 7;       // 16-col block index within the row group
    const int h  = tid >> 2;      // row this lane owns (= 2g + bit2)
    const int q  = tid & 3;       // lane role
    const int p  = q & 1;         // this lane's batch
    const int hiRowi = (tid >> 2) & 1;
    const int b0 = blockIdx.x * NB;
    const int vbase = 16 * c + 4 * (c >> 1);          // padded float offset of col block
    const int hoff = (h >> 5) * PAD + (h & 31);       // padded scalar index for row h

    // ---- stage x rows into smem (.x components)
    {
        const float* xg0 = x + (size_t)b0 * SS;
        const float* xg1 = xg0 + SS;
#pragma unroll
        for (int k = 0; k < SS / NTHREADS; k++) {
            const int s = tid + k * NTHREADS;
            xe[0][s].x = xg0[s];
            xe[1][s].x = xg1[s];
        }
    }
    if (tid < HPAD) { hs[0][tid] = 0.0f; hs[1][tid] = 0.0f; }
    __syncthreads();

    // ---- precompute event weights into xe[.].y AND the event_weights output
    {
        const float wev0 = W_ev[0], wev1 = W_ev[1], bev = b_ev[0];
        float* out_ew = out + BB;
#pragma unroll
        for (int k = 0; k < SS / NTHREADS; k++) {
            const int s = tid + k * NTHREADS;
#pragma unroll
            for (int b = 0; b < NB; b++) {
                float e = 0.0f;
                if (s > 0) {
                    float t = tanha(0.5f * (wev0 * xe[b][s].x + wev1 * xe[b][s - 1].x + bev));
                    e = fmaf(0.5f, t, 0.5f);
                }
                xe[b][s].y = e;
                out_ew[(size_t)(b0 + b) * SS + s] = e;
            }
        }
    }

    // ---- weights into registers, slot-permuted: slot 0 = OWN row (2g + bit2)
    ulonglong2 wa[2][4], wr[2][4], wc[2][4];
#pragma unroll
    for (int j = 0; j < 2; j++) {
        const int row = 2 * g + (hiRowi ^ j);
        const ulonglong2* Wa = reinterpret_cast<const ulonglong2*>(W_att + row * HH + 16 * c);
        const ulonglong2* Wr = reinterpret_cast<const ulonglong2*>(W_rec + row * HH + 16 * c);
        const ulonglong2* Wc = reinterpret_cast<const ulonglong2*>(W_acc + row * HH + 16 * c);
#pragma unroll
        for (int k = 0; k < 4; k++) { wa[j][k] = Wa[k]; wr[j][k] = Wr[k]; wc[j][k] = Wc[k]; }
    }
    // Lane-role-folded scalars.
    const float pA_bias = (q < 2) ? b_att[h] : b_acc[h];   // phase A bias
    const float brec = b_rec[h];
    const float win  = W_in[h];
    const float bin  = b_in[h];
    const float itau = 1.0f / fminf(fmaxf(tau[h], 0.1f), 10.0f);

    // Batch-ordered pointers: own batch first (batch fold happens at xor1).
    const float* hAf = &hs[p][vbase];
    const float* hAs = &hs[p ^ 1][vbase];
    const float* hBf = &hatts[p][vbase];
    const float* hBs = &hatts[p ^ 1][vbase];
    const float2* xep = &xe[p][0];

    float hprev = 0.0f;  // h[p][h] carried in a register
    float accq = 0.0f;   // acc state: q2 holds acc[b0], q3 holds acc[b1]
    float ewpq = 0.0f;   // previous step's event weight for this lane's batch

    __syncthreads();

#pragma unroll 1
    for (int s = 0; s < SS; s++) {
        const float2 xev = xep[s];   // (x_t, ew_t) for this lane's batch

        // ---- phase A: att + acc matvecs on h_s (own batch, then other)
        float PAo, PCo, PAx, PCx;
        passA(wa, wc, hAf, PAo, PCo);
        passA(wa, wc, hAs, PAx, PCx);
        const float A = PAo + shx(PAx, 1);   // full att dot (row h, batch p)
        const float C = PCo + shx(PCx, 1);   // full acc dot (row h, batch p)

        // lane roles: q0->att(b0), q1->att(b1), q2->acc-tanh(b0), q3->acc-tanh(b1)
        const float inA = ((q & 2) ? C : A) + pA_bias;
        const float tA = tanha((q < 2) ? 0.5f * inA : inA);
        const float vA = (q < 2) ? fmaf(0.5f, tA, 0.5f) : tA;

        if (q < 2) hatts[p][hoff] = hprev * vA;  // q0 writes b0, q1 writes b1
        accq = 0.9f * accq + 0.1f * vA * ewpq;   // meaningful on q2/q3 only
        __syncthreads();

        // ---- phase B: recurrence matvec on h*att, state update
        const float PRo = passB(wr, hBf);
        const float PRx = passB(wr, hBs);
        const float R = PRo + shx(PRx, 1);       // full rec dot (row h, batch p)

        // lane roles: q0->rec(b0), q1->rec(b1), q2->ic(b0), q3->ic(b1)
        const float inB = (q & 2) ? fmaf(win, xev.x, bin) : (R + brec);
        const float tB = tanha(inB);
        const float icx = shx(tB, 2);            // q0<-ic0, q1<-ic1
        const float hn = hprev + DT * ((icx + tB - hprev) * itau) * (1.0f + xev.y);
        if (q < 2) hs[p][hoff] = hn;             // q0 writes b0, q1 writes b1
        hprev = hn;
        ewpq = xev.y;
        __syncthreads();
    }

    // ---- trailing acc update: tanh(W_acc @ h_S) with ew_{S-1}
    {
        float PAo, PCo, PAx, PCx;
        passA(wa, wc, hAf, PAo, PCo);
        passA(wa, wc, hAs, PAx, PCx);
        const float C = PCo + shx(PCx, 1);
        const float t = tanha(C + pA_bias);      // valid on q2/q3 (bias = bacc)
        accq = 0.9f * accq + 0.1f * t * ewpq;
    }

    // ---- epilogue: out[b] = (h_f + acc_f) . W_out + b_out
    if (q & 2) hatts[p][hoff] = accq;   // q2 -> acc[b0], q3 -> acc[b1]
    __syncthreads();
    const int w = tid >> 5, l = tid & 31;
    if (w < NB) {
        float pacc = 0.0f;
#pragma unroll
        for (int i = 0; i < HH / 32; i++) {
            const int jo = i * PAD + l;
            pacc += (hs[w][jo] + hatts[w][jo]) * W_out[l + 32 * i];
        }
#pragma unroll
        for (int o = 16; o; o >>= 1) pacc += shx(pacc, o);
        if (l == 0) out[b0 + w] = pacc + b_out[0];
    }
}

extern "C" void kernel_launch(void* const* d_in, const int* in_sizes, int n_in,
                              void* d_out, int out_size) {
    const float* x     = (const float*)d_in[0];
    const float* W_in  = (const float*)d_in[1];
    const float* b_in  = (const float*)d_in[2];
    const float* W_rec = (const float*)d_in[3];
    const float* b_rec = (const float*)d_in[4];
    const float* tau   = (const float*)d_in[5];
    const float* W_att = (const float*)d_in[6];
    const float* b_att = (const float*)d_in[7];
    const float* W_ev  = (const float*)d_in[8];
    const float* b_ev  = (const float*)d_in[9];
    const float* W_acc = (const float*)d_in[10];
    const float* b_acc = (const float*)d_in[11];
    const float* W_out = (const float*)d_in[12];
    const float* b_out = (const float*)d_in[13];
    float* out = (float*)d_out;

    liquid_scan_kernel<<<BB / NB, NTHREADS>>>(x, W_in, b_in, W_rec, b_rec, tau,
                                              W_att, b_att, W_ev, b_ev,
                                              W_acc, b_acc, W_out, b_out, out);
}